// round 1
// baseline (speedup 1.0000x reference)
#include <cuda_runtime.h>

#define N_NODES 32768
#define N_EDGES 524288
#define F_DIM   64
#define D_DIM   64
#define ED_DIM  32
#define L_LAYERS 6
#define TOT (N_EDGES + N_NODES)   // edges + self loops

// ---------------- scratch (static device globals; no allocation) -------------
__device__ float g_h   [N_NODES * D_DIM];
__device__ float g_h2  [N_NODES * D_DIM];
__device__ float g_hm  [N_NODES * D_DIM];
__device__ float g_xh  [N_NODES * 128];      // [N, H*C]
__device__ float g_asd [N_NODES * 4];        // per node: as_h0, as_h1, ad_h0, ad_h1
__device__ float g_ae  [TOT * 2];            // per (edge, head) attention-edge logit
__device__ float g_loop[N_NODES * ED_DIM];   // mean incoming edge_attr (self-loop attr)
__device__ float g_ve  [L_LAYERS * 2 * ED_DIM]; // lin_edge_W @ att_edge, per layer/head
__device__ float g_wbuf[TOT * 2];            // softmax scratch (CSR slot order)
__device__ float g_pspd[N_NODES * 128];      // [N, ps(64) | pd(64)] for edge head
__device__ int   g_deg [N_NODES];
__device__ int   g_rowptr[N_NODES + 1];
__device__ int   g_cnt [N_NODES];
__device__ int   g_csr_src[TOT];
__device__ int   g_csr_eid[TOT];

// ---------------- kernels ----------------------------------------------------

__global__ void k_zero() {
    int stride = gridDim.x * blockDim.x;
    int i = blockIdx.x * blockDim.x + threadIdx.x;
    for (int j = i; j < N_NODES * ED_DIM; j += stride) g_loop[j] = 0.f;
    if (i < N_NODES) { g_deg[i] = 0; g_cnt[i] = 0; }
}

// warp per edge: count degree + accumulate edge_attr sums per dst
__global__ void k_deg(const int* __restrict__ ei, const float* __restrict__ ea) {
    int gw   = (blockIdx.x * blockDim.x + threadIdx.x) >> 5;
    int lane = threadIdx.x & 31;
    if (gw >= N_EDGES) return;
    int dst = ei[N_EDGES + gw];
    atomicAdd(&g_loop[dst * ED_DIM + lane], ea[gw * ED_DIM + lane]);
    if (lane == 0) atomicAdd(&g_deg[dst], 1);
}

__global__ void k_loopdiv() {
    int i = blockIdx.x * blockDim.x + threadIdx.x;
    if (i >= N_NODES * ED_DIM) return;
    int n = i / ED_DIM;
    float d = (float)g_deg[n];
    g_loop[i] = g_loop[i] / fmaxf(d, 1.f);
}

// exclusive scan of (deg+1) over 32768 nodes; single block of 1024 threads
__global__ void k_scan() {
    __shared__ int sm[1024];
    int t = threadIdx.x;
    int base = t * 32;
    int w[32]; int s = 0;
    #pragma unroll
    for (int i = 0; i < 32; i++) { w[i] = g_deg[base + i] + 1; s += w[i]; }
    sm[t] = s; __syncthreads();
    for (int off = 1; off < 1024; off <<= 1) {
        int v = (t >= off) ? sm[t - off] : 0;
        __syncthreads();
        sm[t] += v;
        __syncthreads();
    }
    int run = (t == 0) ? 0 : sm[t - 1];
    #pragma unroll
    for (int i = 0; i < 32; i++) { g_rowptr[base + i] = run; run += w[i]; }
    if (t == 1023) g_rowptr[N_NODES] = run;
}

// place edges into CSR; self loop takes the last slot of each row
__global__ void k_place(const int* __restrict__ ei) {
    int i = blockIdx.x * blockDim.x + threadIdx.x;
    if (i < N_EDGES) {
        int dst = ei[N_EDGES + i];
        int pos = g_rowptr[dst] + atomicAdd(&g_cnt[dst], 1);
        g_csr_src[pos] = ei[i];
        g_csr_eid[pos] = i;
    } else if (i < TOT) {
        int n = i - N_EDGES;
        int pos = g_rowptr[n] + g_deg[n];
        g_csr_src[pos] = n;
        g_csr_eid[pos] = N_EDGES + n;
    }
}

// ve[l,h,:] = lin_edge_W[l,:,h*64:(h+1)*64] @ att_edge[l,h,:]
__global__ void k_ve(const float* __restrict__ linE, const float* __restrict__ attE) {
    int i = threadIdx.x;
    if (i >= L_LAYERS * 2 * ED_DIM) return;
    int l = i / (2 * ED_DIM);
    int r = i % (2 * ED_DIM);
    int h = r / ED_DIM;
    int ed = r % ED_DIM;
    const float* W = linE + l * ED_DIM * 128 + ed * 128 + h * 64;
    const float* a = attE + l * 128 + h * 64;
    float s = 0.f;
    #pragma unroll
    for (int c = 0; c < 64; c++) s += W[c] * a[c];
    g_ve[i] = s;
}

// h = x @ embed_W + b ; one thread per output element
__global__ void k_embed(const float* __restrict__ x, const float* __restrict__ W,
                        const float* __restrict__ b, float* __restrict__ hout) {
    __shared__ float sW[64 * 64];
    for (int i = threadIdx.x; i < 64 * 64; i += blockDim.x) sW[i] = W[i];
    __syncthreads();
    int idx = blockIdx.x * blockDim.x + threadIdx.x;
    int n = idx >> 6, c = idx & 63;
    if (n >= N_NODES) return;
    const float4* xr = (const float4*)(x + n * F_DIM);
    float acc = b[c];
    #pragma unroll
    for (int f4 = 0; f4 < 16; f4++) {
        float4 v = xr[f4];
        acc += v.x * sW[(4 * f4 + 0) * 64 + c];
        acc += v.y * sW[(4 * f4 + 1) * 64 + c];
        acc += v.z * sW[(4 * f4 + 2) * 64 + c];
        acc += v.w * sW[(4 * f4 + 3) * 64 + c];
    }
    hout[n * 64 + c] = acc;
}

// LayerNorm + manual modulation; warp per node
__global__ void k_ln(const float* __restrict__ hin, const float* __restrict__ g,
                     const float* __restrict__ bta, const float* __restrict__ mg,
                     const float* __restrict__ mb) {
    int warp = (blockIdx.x * blockDim.x + threadIdx.x) >> 5;
    int lane = threadIdx.x & 31;
    if (warp >= N_NODES) return;
    const float* hr = hin + warp * 64;
    float v0 = hr[lane], v1 = hr[lane + 32];
    float s = v0 + v1;
    #pragma unroll
    for (int o = 16; o; o >>= 1) s += __shfl_xor_sync(~0u, s, o);
    float mu = s * (1.f / 64.f);
    float d0 = v0 - mu, d1 = v1 - mu;
    float q = d0 * d0 + d1 * d1;
    #pragma unroll
    for (int o = 16; o; o >>= 1) q += __shfl_xor_sync(~0u, q, o);
    float rs = rsqrtf(q * (1.f / 64.f) + 1e-5f);
    float o0 = mg[lane]      * (g[lane]      * d0 * rs + bta[lane])      + mb[lane];
    float o1 = mg[lane + 32] * (g[lane + 32] * d1 * rs + bta[lane + 32]) + mb[lane + 32];
    g_hm[warp * 64 + lane]      = o0;
    g_hm[warp * 64 + lane + 32] = o1;
}

// xh = hm @ lin_W[l]  (64 -> 128); 16 nodes per block, W cached in smem
__global__ void k_xh(const float* __restrict__ W) {
    __shared__ float sW[64 * 128];
    for (int i = threadIdx.x; i < 8192; i += 256) sW[i] = W[i];
    __syncthreads();
    int j   = threadIdx.x & 127;
    int sub = threadIdx.x >> 7;
    int n0  = blockIdx.x * 16;
    #pragma unroll
    for (int k = 0; k < 8; k++) {
        int n = n0 + sub + 2 * k;
        const float4* h4 = (const float4*)(g_hm + n * 64);
        float acc = 0.f;
        #pragma unroll
        for (int d4 = 0; d4 < 16; d4++) {
            float4 v = h4[d4];
            acc += v.x * sW[(4 * d4 + 0) * 128 + j];
            acc += v.y * sW[(4 * d4 + 1) * 128 + j];
            acc += v.z * sW[(4 * d4 + 2) * 128 + j];
            acc += v.w * sW[(4 * d4 + 3) * 128 + j];
        }
        g_xh[n * 128 + j] = acc;
    }
}

// a_s / a_d per (node, head); one thread per (n, q)
__global__ void k_asd(const float* __restrict__ aS, const float* __restrict__ aD) {
    int idx = blockIdx.x * blockDim.x + threadIdx.x;
    if (idx >= N_NODES * 4) return;
    int n = idx >> 2, q = idx & 3;      // q: 0=as_h0 1=as_h1 2=ad_h0 3=ad_h1
    int h = q & 1;
    const float* a  = ((q < 2) ? aS : aD) + h * 64;
    const float* xr = g_xh + n * 128 + h * 64;
    float s = 0.f;
    #pragma unroll
    for (int c = 0; c < 64; c++) s += xr[c] * a[c];
    g_asd[n * 4 + q] = s;
}

// a_e for all E real edges + N self loops, this layer
__global__ void k_ae(const float* __restrict__ ea, int l) {
    int e = blockIdx.x * blockDim.x + threadIdx.x;
    if (e >= TOT) return;
    const float* v = (e < N_EDGES) ? (ea + (size_t)e * ED_DIM)
                                   : (g_loop + (size_t)(e - N_EDGES) * ED_DIM);
    const float* ve0 = g_ve + l * 2 * ED_DIM;
    float s0 = 0.f, s1 = 0.f;
    #pragma unroll
    for (int k = 0; k < ED_DIM; k++) {
        float x = v[k];
        s0 += x * ve0[k];
        s1 += x * ve0[ED_DIM + k];
    }
    g_ae[e * 2]     = s0;
    g_ae[e * 2 + 1] = s1;
}

// fused segment-softmax + weighted aggregation + head-mean + bias + relu
// warp per destination node, edges via CSR
__global__ void k_attn(float* __restrict__ hout, const float* __restrict__ gbias) {
    int n    = (blockIdx.x * blockDim.x + threadIdx.x) >> 5;
    int lane = threadIdx.x & 31;
    if (n >= N_NODES) return;
    int row = g_rowptr[n], end = g_rowptr[n + 1];
    float ad0 = g_asd[n * 4 + 2], ad1 = g_asd[n * 4 + 3];

    // phase 1: logits -> wbuf, track max
    float m0 = -1e30f, m1 = -1e30f;
    for (int i = row + lane; i < end; i += 32) {
        int s = g_csr_src[i], eid = g_csr_eid[i];
        float a0 = g_asd[s * 4]     + ad0 + g_ae[eid * 2];
        float a1 = g_asd[s * 4 + 1] + ad1 + g_ae[eid * 2 + 1];
        a0 = (a0 > 0.f) ? a0 : 0.2f * a0;
        a1 = (a1 > 0.f) ? a1 : 0.2f * a1;
        g_wbuf[i * 2] = a0; g_wbuf[i * 2 + 1] = a1;
        m0 = fmaxf(m0, a0); m1 = fmaxf(m1, a1);
    }
    #pragma unroll
    for (int o = 16; o; o >>= 1) {
        m0 = fmaxf(m0, __shfl_xor_sync(~0u, m0, o));
        m1 = fmaxf(m1, __shfl_xor_sync(~0u, m1, o));
    }

    // phase 2: exp and sum
    float s0 = 0.f, s1 = 0.f;
    for (int i = row + lane; i < end; i += 32) {
        float e0 = __expf(g_wbuf[i * 2]     - m0);
        float e1 = __expf(g_wbuf[i * 2 + 1] - m1);
        g_wbuf[i * 2] = e0; g_wbuf[i * 2 + 1] = e1;
        s0 += e0; s1 += e1;
    }
    #pragma unroll
    for (int o = 16; o; o >>= 1) {
        s0 += __shfl_xor_sync(~0u, s0, o);
        s1 += __shfl_xor_sync(~0u, s1, o);
    }
    float inv0 = 1.f / (s0 + 1e-16f), inv1 = 1.f / (s1 + 1e-16f);
    __syncwarp();   // make all lanes' wbuf writes visible for phase 3

    // phase 3: aggregate messages (lanes cover the 128 channels)
    float acc0 = 0.f, acc1 = 0.f, acc2 = 0.f, acc3 = 0.f;
    for (int i = row; i < end; i++) {
        int s = g_csr_src[i];
        float w0 = g_wbuf[i * 2] * inv0;
        float w1 = g_wbuf[i * 2 + 1] * inv1;
        const float* xr = g_xh + s * 128;
        acc0 += xr[lane]      * w0;
        acc1 += xr[lane + 32] * w0;
        acc2 += xr[lane + 64] * w1;
        acc3 += xr[lane + 96] * w1;
    }
    float o0 = 0.5f * (acc0 + acc2) + gbias[lane];
    float o1 = 0.5f * (acc1 + acc3) + gbias[lane + 32];
    hout[n * 64 + lane]      = fmaxf(o0, 0.f);
    hout[n * 64 + lane + 32] = fmaxf(o1, 0.f);
}

// ps = h@W1[0:64], pd = h@W1[64:128]; stored [N, ps|pd]
__global__ void k_pspd(const float* __restrict__ hfin, const float* __restrict__ W1) {
    __shared__ float sW[8192];   // sW[d*128+j]: j<64 -> W1[d*64+j], else W1[(64+d)*64+(j-64)]
    for (int i = threadIdx.x; i < 8192; i += 256) {
        int d = i >> 7, j = i & 127;
        sW[i] = (j < 64) ? W1[d * 64 + j] : W1[(64 + d) * 64 + (j - 64)];
    }
    __syncthreads();
    int j   = threadIdx.x & 127;
    int sub = threadIdx.x >> 7;
    int n0  = blockIdx.x * 16;
    #pragma unroll
    for (int k = 0; k < 8; k++) {
        int n = n0 + sub + 2 * k;
        const float4* h4 = (const float4*)(hfin + n * 64);
        float acc = 0.f;
        #pragma unroll
        for (int d4 = 0; d4 < 16; d4++) {
            float4 v = h4[d4];
            acc += v.x * sW[(4 * d4 + 0) * 128 + j];
            acc += v.y * sW[(4 * d4 + 1) * 128 + j];
            acc += v.z * sW[(4 * d4 + 2) * 128 + j];
            acc += v.w * sW[(4 * d4 + 3) * 128 + j];
        }
        g_pspd[n * 128 + j] = acc;
    }
}

// per-edge head: hid = relu(ps[src]+pd[dst]+ea@Ce+b1); out = hid@W2+b2
__global__ void k_head(const int* __restrict__ ei, const float* __restrict__ ea,
                       const float* __restrict__ W1, const float* __restrict__ b1,
                       const float* __restrict__ W2, const float* __restrict__ b2,
                       float* __restrict__ out) {
    __shared__ float sC[32 * 64];
    __shared__ float sW2[64];
    __shared__ float sB1[64];
    for (int i = threadIdx.x; i < 32 * 64; i += blockDim.x) sC[i] = W1[128 * 64 + i];
    if (threadIdx.x < 64) { sW2[threadIdx.x] = W2[threadIdx.x]; sB1[threadIdx.x] = b1[threadIdx.x]; }
    __syncthreads();
    int e    = (blockIdx.x * blockDim.x + threadIdx.x) >> 5;
    int lane = threadIdx.x & 31;
    if (e >= N_EDGES) return;
    int src = ei[e], dst = ei[N_EDGES + e];
    float t0 = g_pspd[src * 128 + lane]      + g_pspd[dst * 128 + 64 + lane]      + sB1[lane];
    float t1 = g_pspd[src * 128 + lane + 32] + g_pspd[dst * 128 + 64 + lane + 32] + sB1[lane + 32];
    const float* er = ea + (size_t)e * 32;
    #pragma unroll
    for (int k = 0; k < 32; k++) {
        float x = er[k];
        t0 += x * sC[k * 64 + lane];
        t1 += x * sC[k * 64 + lane + 32];
    }
    t0 = fmaxf(t0, 0.f); t1 = fmaxf(t1, 0.f);
    float r = t0 * sW2[lane] + t1 * sW2[lane + 32];
    #pragma unroll
    for (int o = 16; o; o >>= 1) r += __shfl_xor_sync(~0u, r, o);
    if (lane == 0) out[e] = r + b2[0];
}

// ---------------- launch ------------------------------------------------------

extern "C" void kernel_launch(void* const* d_in, const int* in_sizes, int n_in,
                              void* d_out, int out_size) {
    const float* x      = (const float*)d_in[0];
    const int*   ei     = (const int*)  d_in[1];
    const float* ea     = (const float*)d_in[2];
    const float* mgamma = (const float*)d_in[3];
    const float* mbeta  = (const float*)d_in[4];
    const float* embW   = (const float*)d_in[5];
    const float* embB   = (const float*)d_in[6];
    const float* lng    = (const float*)d_in[7];
    const float* lnb    = (const float*)d_in[8];
    const float* linW   = (const float*)d_in[9];
    const float* linEW  = (const float*)d_in[10];
    const float* attS   = (const float*)d_in[11];
    const float* attD   = (const float*)d_in[12];
    const float* attE   = (const float*)d_in[13];
    const float* gbias  = (const float*)d_in[14];
    const float* W1     = (const float*)d_in[15];
    const float* b1     = (const float*)d_in[16];
    const float* W2     = (const float*)d_in[17];
    const float* b2     = (const float*)d_in[18];
    float* out = (float*)d_out;

    float *ph, *ph2;
    cudaGetSymbolAddress((void**)&ph,  g_h);
    cudaGetSymbolAddress((void**)&ph2, g_h2);

    k_zero<<<4096, 256>>>();
    k_deg<<<N_EDGES * 32 / 256, 256>>>(ei, ea);
    k_loopdiv<<<(N_NODES * ED_DIM + 255) / 256, 256>>>();
    k_scan<<<1, 1024>>>();
    k_place<<<(TOT + 255) / 256, 256>>>(ei);
    k_ve<<<1, 384>>>(linEW, attE);
    k_embed<<<N_NODES * 64 / 256, 256>>>(x, embW, embB, ph);

    float* hin = ph;
    float* hout = ph2;
    for (int l = 0; l < L_LAYERS; l++) {
        k_ln<<<N_NODES * 32 / 256, 256>>>(hin, lng + l * 64, lnb + l * 64,
                                          mgamma + l * 64, mbeta + l * 64);
        k_xh<<<N_NODES / 16, 256>>>(linW + l * 64 * 128);
        k_asd<<<N_NODES * 4 / 256, 256>>>(attS + l * 128, attD + l * 128);
        k_ae<<<(TOT + 255) / 256, 256>>>(ea, l);
        k_attn<<<N_NODES * 32 / 256, 256>>>(hout, gbias + l * 64);
        float* t = hin; hin = hout; hout = t;
    }
    k_pspd<<<N_NODES / 16, 256>>>(hin, W1);
    k_head<<<N_EDGES * 32 / 256, 256>>>(ei, ea, W1, b1, W2, b2, out);
}

// round 3
// speedup vs baseline: 2.0120x; 2.0120x over previous
#include <cuda_runtime.h>

#define N_NODES 32768
#define N_EDGES 524288
#define F_DIM   64
#define D_DIM   64
#define ED_DIM  32
#define L_LAYERS 6
#define TOT (N_EDGES + N_NODES)   // edges + self loops

// ---------------- scratch (static device globals; no allocation) -------------
__device__ float g_h      [N_NODES * D_DIM];
__device__ float g_h2     [N_NODES * D_DIM];
__device__ float g_hm     [N_NODES * D_DIM];
__device__ float g_xh     [N_NODES * 128];      // [N, H*C]
__device__ float g_asd    [N_NODES * 4];        // as_h0, as_h1, ad_h0, ad_h1
__device__ float g_ae_all [N_EDGES * 12];       // per edge: 6 layers x 2 heads
__device__ float g_ae_loop[N_NODES * 12];       // self-loop logits (mean of incoming)
__device__ float g_ve     [L_LAYERS * 2 * ED_DIM]; // lin_edge_W @ att_edge
__device__ float g_wbuf   [TOT * 2];            // softmax scratch (slow path only)
__device__ float g_pspd   [N_NODES * 128];      // [N, ps(64) | pd(64)]
__device__ int   g_deg    [N_NODES];
__device__ int   g_rowptr [N_NODES + 1];
__device__ int   g_cnt    [N_NODES];
__device__ int   g_csr_src[TOT];
__device__ int   g_csr_eid[TOT];

// ---------------- setup kernels ----------------------------------------------

__global__ void k_zero() {
    int i = blockIdx.x * blockDim.x + threadIdx.x;
    if (i < N_NODES) { g_deg[i] = 0; g_cnt[i] = 0; }
}

__global__ void k_deg(const int* __restrict__ ei) {
    int e = blockIdx.x * blockDim.x + threadIdx.x;
    if (e >= N_EDGES) return;
    atomicAdd(&g_deg[ei[N_EDGES + e]], 1);
}

// exclusive scan of (deg+1); 1024 threads, warp-shuffle based
__global__ void k_scan() {
    __shared__ int wsum[32];
    int t = threadIdx.x, lane = t & 31, w = t >> 5;
    int base = t * 32;
    int vals[32]; int s = 0;
    #pragma unroll
    for (int i = 0; i < 32; i++) { vals[i] = g_deg[base + i] + 1; s += vals[i]; }
    int inc = s;
    #pragma unroll
    for (int off = 1; off < 32; off <<= 1) {
        int v = __shfl_up_sync(~0u, inc, off);
        if (lane >= off) inc += v;
    }
    if (lane == 31) wsum[w] = inc;
    __syncthreads();
    if (w == 0) {
        int v = wsum[lane], vi = v;
        #pragma unroll
        for (int off = 1; off < 32; off <<= 1) {
            int u = __shfl_up_sync(~0u, vi, off);
            if (lane >= off) vi += u;
        }
        wsum[lane] = vi;
    }
    __syncthreads();
    int run = (w > 0 ? wsum[w - 1] : 0) + (inc - s);
    #pragma unroll
    for (int i = 0; i < 32; i++) { g_rowptr[base + i] = run; run += vals[i]; }
    if (t == 1023) g_rowptr[N_NODES] = run;
}

__global__ void k_place(const int* __restrict__ ei) {
    int i = blockIdx.x * blockDim.x + threadIdx.x;
    if (i < N_EDGES) {
        int dst = ei[N_EDGES + i];
        int pos = g_rowptr[dst] + atomicAdd(&g_cnt[dst], 1);
        g_csr_src[pos] = ei[i];
        g_csr_eid[pos] = i;
    } else if (i < TOT) {
        int n = i - N_EDGES;
        int pos = g_rowptr[n] + g_deg[n];
        g_csr_src[pos] = n;
        g_csr_eid[pos] = N_EDGES + n;
    }
}

// ve[l,h,:] = lin_edge_W[l,:,h*64:(h+1)*64] @ att_edge[l,h,:]
__global__ void k_ve(const float* __restrict__ linE, const float* __restrict__ attE) {
    int i = threadIdx.x;
    if (i >= L_LAYERS * 64) return;
    int l = i >> 6, r = i & 63;
    int h = r >> 5, ed = r & 31;
    const float* W = linE + l * ED_DIM * 128 + ed * 128 + h * 64;
    const float* a = attE + l * 128 + h * 64;
    float s = 0.f;
    #pragma unroll
    for (int c = 0; c < 64; c++) s += W[c] * a[c];
    g_ve[l * 64 + h * 32 + ed] = s;
}

// all-layer edge attention logits in one pass over edge_attr
__global__ void k_ae_all(const float* __restrict__ ea) {
    __shared__ float sv[384];
    for (int i = threadIdx.x; i < 384; i += blockDim.x) sv[i] = g_ve[i];   // FIXED: full load
    __syncthreads();
    int e = blockIdx.x * blockDim.x + threadIdx.x;
    if (e >= N_EDGES) return;
    float v[32];
    const float4* p = (const float4*)(ea + (size_t)e * 32);
    #pragma unroll
    for (int i = 0; i < 8; i++) {
        float4 q = p[i];
        v[4 * i] = q.x; v[4 * i + 1] = q.y; v[4 * i + 2] = q.z; v[4 * i + 3] = q.w;
    }
    float o[12];
    #pragma unroll
    for (int c = 0; c < 12; c++) {
        int l = c >> 1, h = c & 1;
        const float* vv = sv + l * 64 + h * 32;
        float s = 0.f;
        #pragma unroll
        for (int k = 0; k < 32; k++) s += v[k] * vv[k];
        o[c] = s;
    }
    float4* op = (float4*)(g_ae_all + (size_t)e * 12);
    op[0] = make_float4(o[0], o[1], o[2], o[3]);
    op[1] = make_float4(o[4], o[5], o[6], o[7]);
    op[2] = make_float4(o[8], o[9], o[10], o[11]);
}

// self-loop logits: mean over incoming edges (linearity of a_e in edge_attr)
__global__ void k_aeloop() {
    int idx = blockIdx.x * blockDim.x + threadIdx.x;
    if (idx >= N_NODES * 12) return;
    int n = idx / 12, c = idx % 12;
    int row = g_rowptr[n], deg = g_deg[n];
    float s = 0.f;
    for (int i = 0; i < deg; i++)
        s += g_ae_all[(size_t)g_csr_eid[row + i] * 12 + c];
    g_ae_loop[n * 12 + c] = s / fmaxf((float)deg, 1.f);
}

// ---------------- dense kernels (register-tiled, node per thread) ------------

__global__ void k_embed(const float* __restrict__ x, const float* __restrict__ W,
                        const float* __restrict__ b, float* __restrict__ hout) {
    __shared__ float sW[64 * 64];
    __shared__ float sB[64];
    for (int i = threadIdx.x; i < 64 * 64; i += 256) sW[i] = W[i];
    if (threadIdx.x < 64) sB[threadIdx.x] = b[threadIdx.x];
    __syncthreads();
    int n = blockIdx.x * 256 + threadIdx.x;
    float h[64];
    const float4* hp = (const float4*)(x + (size_t)n * 64);
    #pragma unroll
    for (int i = 0; i < 16; i++) {
        float4 q = hp[i];
        h[4 * i] = q.x; h[4 * i + 1] = q.y; h[4 * i + 2] = q.z; h[4 * i + 3] = q.w;
    }
    #pragma unroll 2
    for (int jg = 0; jg < 16; jg++) {
        float a0 = sB[jg * 4], a1 = sB[jg * 4 + 1], a2 = sB[jg * 4 + 2], a3 = sB[jg * 4 + 3];
        #pragma unroll
        for (int d = 0; d < 64; d++) {
            float4 w = *(const float4*)&sW[d * 64 + jg * 4];
            a0 += h[d] * w.x; a1 += h[d] * w.y; a2 += h[d] * w.z; a3 += h[d] * w.w;
        }
        *(float4*)&hout[(size_t)n * 64 + jg * 4] = make_float4(a0, a1, a2, a3);
    }
}

// LayerNorm + manual modulation; warp per node
__global__ void k_ln(const float* __restrict__ hin, const float* __restrict__ g,
                     const float* __restrict__ bta, const float* __restrict__ mg,
                     const float* __restrict__ mb) {
    int warp = (blockIdx.x * blockDim.x + threadIdx.x) >> 5;
    int lane = threadIdx.x & 31;
    if (warp >= N_NODES) return;
    const float* hr = hin + (size_t)warp * 64;
    float v0 = hr[lane], v1 = hr[lane + 32];
    float s = v0 + v1;
    #pragma unroll
    for (int o = 16; o; o >>= 1) s += __shfl_xor_sync(~0u, s, o);
    float mu = s * (1.f / 64.f);
    float d0 = v0 - mu, d1 = v1 - mu;
    float q = d0 * d0 + d1 * d1;
    #pragma unroll
    for (int o = 16; o; o >>= 1) q += __shfl_xor_sync(~0u, q, o);
    float rs = rsqrtf(q * (1.f / 64.f) + 1e-5f);
    float o0 = mg[lane]      * (g[lane]      * d0 * rs + bta[lane])      + mb[lane];
    float o1 = mg[lane + 32] * (g[lane + 32] * d1 * rs + bta[lane + 32]) + mb[lane + 32];
    g_hm[(size_t)warp * 64 + lane]      = o0;
    g_hm[(size_t)warp * 64 + lane + 32] = o1;
}

// xh = hm @ lin_W[l] (64 -> 128) fused with a_s/a_d dot products
__global__ void k_xh(const float* __restrict__ W, const float* __restrict__ attS,
                     const float* __restrict__ attD) {
    __shared__ float sW[64 * 128];
    __shared__ float sA[256];     // [0:128) att_src, [128:256) att_dst
    for (int i = threadIdx.x; i < 8192; i += 256) sW[i] = W[i];
    if (threadIdx.x < 128) {
        sA[threadIdx.x] = attS[threadIdx.x];
        sA[128 + threadIdx.x] = attD[threadIdx.x];
    }
    __syncthreads();
    int n = blockIdx.x * 256 + threadIdx.x;
    float h[64];
    const float4* hp = (const float4*)(g_hm + (size_t)n * 64);
    #pragma unroll
    for (int i = 0; i < 16; i++) {
        float4 q = hp[i];
        h[4 * i] = q.x; h[4 * i + 1] = q.y; h[4 * i + 2] = q.z; h[4 * i + 3] = q.w;
    }
    float as0 = 0.f, as1 = 0.f, ad0 = 0.f, ad1 = 0.f;
    for (int jg = 0; jg < 32; jg++) {
        float a0 = 0.f, a1 = 0.f, a2 = 0.f, a3 = 0.f;
        #pragma unroll
        for (int d = 0; d < 64; d++) {
            float4 w = *(const float4*)&sW[d * 128 + jg * 4];
            a0 += h[d] * w.x; a1 += h[d] * w.y; a2 += h[d] * w.z; a3 += h[d] * w.w;
        }
        *(float4*)&g_xh[(size_t)n * 128 + jg * 4] = make_float4(a0, a1, a2, a3);
        int j = jg * 4;
        float s = a0 * sA[j] + a1 * sA[j + 1] + a2 * sA[j + 2] + a3 * sA[j + 3];
        float d = a0 * sA[128 + j] + a1 * sA[128 + j + 1] + a2 * sA[128 + j + 2] + a3 * sA[128 + j + 3];
        if (jg < 16) { as0 += s; ad0 += d; } else { as1 += s; ad1 += d; }
    }
    float4* ap = (float4*)&g_asd[(size_t)n * 4];
    *ap = make_float4(as0, as1, ad0, ad1);
}

// ---------------- fused segment softmax + aggregation ------------------------

__global__ void k_attn(float* __restrict__ hout, const float* __restrict__ gbias, int l) {
    int n    = (blockIdx.x * blockDim.x + threadIdx.x) >> 5;
    int lane = threadIdx.x & 31;
    if (n >= N_NODES) return;
    int row = g_rowptr[n], end = g_rowptr[n + 1];
    int cnt = end - row;
    float ad0 = g_asd[n * 4 + 2], ad1 = g_asd[n * 4 + 3];

    float acc0 = 0.f, acc1 = 0.f, acc2 = 0.f, acc3 = 0.f;

    if (cnt <= 32) {
        // -------- fast path: everything in lane registers --------
        int sidx = 0;
        float l0 = -1e30f, l1 = -1e30f;
        if (lane < cnt) {
            int slot = row + lane;
            sidx = g_csr_src[slot];
            int eid = g_csr_eid[slot];
            float b0, b1;
            if (eid < N_EDGES) {
                const float* ap = g_ae_all + (size_t)eid * 12 + l * 2;
                b0 = ap[0]; b1 = ap[1];
            } else {
                const float* ap = g_ae_loop + (size_t)n * 12 + l * 2;
                b0 = ap[0]; b1 = ap[1];
            }
            float2 as = *(const float2*)&g_asd[sidx * 4];
            l0 = as.x + ad0 + b0;
            l1 = as.y + ad1 + b1;
            l0 = (l0 > 0.f) ? l0 : 0.2f * l0;
            l1 = (l1 > 0.f) ? l1 : 0.2f * l1;
        }
        float m0 = l0, m1 = l1;
        #pragma unroll
        for (int o = 16; o; o >>= 1) {
            m0 = fmaxf(m0, __shfl_xor_sync(~0u, m0, o));
            m1 = fmaxf(m1, __shfl_xor_sync(~0u, m1, o));
        }
        float e0 = (lane < cnt) ? __expf(l0 - m0) : 0.f;
        float e1 = (lane < cnt) ? __expf(l1 - m1) : 0.f;
        float s0 = e0, s1 = e1;
        #pragma unroll
        for (int o = 16; o; o >>= 1) {
            s0 += __shfl_xor_sync(~0u, s0, o);
            s1 += __shfl_xor_sync(~0u, s1, o);
        }
        float w0 = e0 / (s0 + 1e-16f);
        float w1 = e1 / (s1 + 1e-16f);
        for (int i = 0; i < cnt; i++) {
            int   si  = __shfl_sync(~0u, sidx, i);
            float w0i = __shfl_sync(~0u, w0, i);
            float w1i = __shfl_sync(~0u, w1, i);
            const float* xr = g_xh + (size_t)si * 128;
            acc0 += xr[lane]      * w0i;
            acc1 += xr[lane + 32] * w0i;
            acc2 += xr[lane + 64] * w1i;
            acc3 += xr[lane + 96] * w1i;
        }
    } else {
        // -------- slow path: spill logits to wbuf --------
        float m0 = -1e30f, m1 = -1e30f;
        for (int i = row + lane; i < end; i += 32) {
            int s = g_csr_src[i], eid = g_csr_eid[i];
            float b0, b1;
            if (eid < N_EDGES) {
                const float* ap = g_ae_all + (size_t)eid * 12 + l * 2;
                b0 = ap[0]; b1 = ap[1];
            } else {
                const float* ap = g_ae_loop + (size_t)n * 12 + l * 2;
                b0 = ap[0]; b1 = ap[1];
            }
            float2 as = *(const float2*)&g_asd[s * 4];
            float a0 = as.x + ad0 + b0;
            float a1 = as.y + ad1 + b1;
            a0 = (a0 > 0.f) ? a0 : 0.2f * a0;
            a1 = (a1 > 0.f) ? a1 : 0.2f * a1;
            g_wbuf[i * 2] = a0; g_wbuf[i * 2 + 1] = a1;
            m0 = fmaxf(m0, a0); m1 = fmaxf(m1, a1);
        }
        #pragma unroll
        for (int o = 16; o; o >>= 1) {
            m0 = fmaxf(m0, __shfl_xor_sync(~0u, m0, o));
            m1 = fmaxf(m1, __shfl_xor_sync(~0u, m1, o));
        }
        float s0 = 0.f, s1 = 0.f;
        for (int i = row + lane; i < end; i += 32) {
            float e0 = __expf(g_wbuf[i * 2]     - m0);
            float e1 = __expf(g_wbuf[i * 2 + 1] - m1);
            g_wbuf[i * 2] = e0; g_wbuf[i * 2 + 1] = e1;
            s0 += e0; s1 += e1;
        }
        #pragma unroll
        for (int o = 16; o; o >>= 1) {
            s0 += __shfl_xor_sync(~0u, s0, o);
            s1 += __shfl_xor_sync(~0u, s1, o);
        }
        float inv0 = 1.f / (s0 + 1e-16f), inv1 = 1.f / (s1 + 1e-16f);
        __syncwarp();
        for (int i = row; i < end; i++) {
            int s = g_csr_src[i];
            float w0 = g_wbuf[i * 2] * inv0;
            float w1 = g_wbuf[i * 2 + 1] * inv1;
            const float* xr = g_xh + (size_t)s * 128;
            acc0 += xr[lane]      * w0;
            acc1 += xr[lane + 32] * w0;
            acc2 += xr[lane + 64] * w1;
            acc3 += xr[lane + 96] * w1;
        }
    }
    float o0 = 0.5f * (acc0 + acc2) + gbias[lane];
    float o1 = 0.5f * (acc1 + acc3) + gbias[lane + 32];
    hout[(size_t)n * 64 + lane]      = fmaxf(o0, 0.f);
    hout[(size_t)n * 64 + lane + 32] = fmaxf(o1, 0.f);
}

// ---------------- edge head ---------------------------------------------------

// ps = h@W1[0:64], pd = h@W1[64:128]; stored [N, ps|pd]
__global__ void k_pspd(const float* __restrict__ hfin, const float* __restrict__ W1) {
    __shared__ float sW[8192];  // sW[d*128+j]: j<64 -> W1[d*64+j] else W1[(64+d)*64+(j-64)]
    for (int i = threadIdx.x; i < 8192; i += 256) {
        int d = i >> 7, j = i & 127;
        sW[i] = (j < 64) ? W1[d * 64 + j] : W1[(64 + d) * 64 + (j - 64)];
    }
    __syncthreads();
    int n = blockIdx.x * 256 + threadIdx.x;
    float h[64];
    const float4* hp = (const float4*)(hfin + (size_t)n * 64);
    #pragma unroll
    for (int i = 0; i < 16; i++) {
        float4 q = hp[i];
        h[4 * i] = q.x; h[4 * i + 1] = q.y; h[4 * i + 2] = q.z; h[4 * i + 3] = q.w;
    }
    for (int jg = 0; jg < 32; jg++) {
        float a0 = 0.f, a1 = 0.f, a2 = 0.f, a3 = 0.f;
        #pragma unroll
        for (int d = 0; d < 64; d++) {
            float4 w = *(const float4*)&sW[d * 128 + jg * 4];
            a0 += h[d] * w.x; a1 += h[d] * w.y; a2 += h[d] * w.z; a3 += h[d] * w.w;
        }
        *(float4*)&g_pspd[(size_t)n * 128 + jg * 4] = make_float4(a0, a1, a2, a3);
    }
}

// per-edge head: hid = relu(ps[src]+pd[dst]+ea@Ce+b1); out = hid@W2+b2
// lane owns output columns (2*lane, 2*lane+1)
__global__ void k_head(const int* __restrict__ ei, const float* __restrict__ ea,
                       const float* __restrict__ W1, const float* __restrict__ b1,
                       const float* __restrict__ W2, const float* __restrict__ b2,
                       float* __restrict__ out) {
    __shared__ float sC[32 * 64];
    __shared__ float sW2[64];
    __shared__ float sB1[64];
    for (int i = threadIdx.x; i < 32 * 64; i += 256) sC[i] = W1[128 * 64 + i];
    if (threadIdx.x < 64) { sW2[threadIdx.x] = W2[threadIdx.x]; sB1[threadIdx.x] = b1[threadIdx.x]; }
    __syncthreads();
    int e    = (blockIdx.x * blockDim.x + threadIdx.x) >> 5;
    int lane = threadIdx.x & 31;
    if (e >= N_EDGES) return;
    int src = ei[e], dst = ei[N_EDGES + e];
    float2 t  = *(const float2*)&g_pspd[(size_t)src * 128 + 2 * lane];
    float2 td = *(const float2*)&g_pspd[(size_t)dst * 128 + 64 + 2 * lane];
    float2 bb = *(const float2*)&sB1[2 * lane];
    t.x += td.x + bb.x;
    t.y += td.y + bb.y;
    float eav = ea[(size_t)e * 32 + lane];
    #pragma unroll
    for (int k = 0; k < 32; k++) {
        float x = __shfl_sync(~0u, eav, k);
        float2 w = *(const float2*)&sC[k * 64 + 2 * lane];
        t.x += x * w.x;
        t.y += x * w.y;
    }
    t.x = fmaxf(t.x, 0.f); t.y = fmaxf(t.y, 0.f);
    float2 w2 = *(const float2*)&sW2[2 * lane];
    float r = t.x * w2.x + t.y * w2.y;
    #pragma unroll
    for (int o = 16; o; o >>= 1) r += __shfl_xor_sync(~0u, r, o);
    if (lane == 0) out[e] = r + b2[0];
}

// ---------------- launch ------------------------------------------------------

extern "C" void kernel_launch(void* const* d_in, const int* in_sizes, int n_in,
                              void* d_out, int out_size) {
    const float* x      = (const float*)d_in[0];
    const int*   ei     = (const int*)  d_in[1];
    const float* ea     = (const float*)d_in[2];
    const float* mgamma = (const float*)d_in[3];
    const float* mbeta  = (const float*)d_in[4];
    const float* embW   = (const float*)d_in[5];
    const float* embB   = (const float*)d_in[6];
    const float* lng    = (const float*)d_in[7];
    const float* lnb    = (const float*)d_in[8];
    const float* linW   = (const float*)d_in[9];
    const float* linEW  = (const float*)d_in[10];
    const float* attS   = (const float*)d_in[11];
    const float* attD   = (const float*)d_in[12];
    const float* attE   = (const float*)d_in[13];
    const float* gbias  = (const float*)d_in[14];
    const float* W1     = (const float*)d_in[15];
    const float* b1     = (const float*)d_in[16];
    const float* W2     = (const float*)d_in[17];
    const float* b2     = (const float*)d_in[18];
    float* out = (float*)d_out;

    float *ph, *ph2;
    cudaGetSymbolAddress((void**)&ph,  g_h);
    cudaGetSymbolAddress((void**)&ph2, g_h2);

    k_zero<<<128, 256>>>();
    k_deg<<<2048, 256>>>(ei);
    k_scan<<<1, 1024>>>();
    k_place<<<(TOT + 255) / 256, 256>>>(ei);
    k_ve<<<1, 384>>>(linEW, attE);
    k_ae_all<<<2048, 256>>>(ea);
    k_aeloop<<<(N_NODES * 12 + 255) / 256, 256>>>();
    k_embed<<<128, 256>>>(x, embW, embB, ph);

    float* hin = ph;
    float* hout = ph2;
    for (int l = 0; l < L_LAYERS; l++) {
        k_ln<<<4096, 256>>>(hin, lng + l * 64, lnb + l * 64,
                            mgamma + l * 64, mbeta + l * 64);
        k_xh<<<128, 256>>>(linW + (size_t)l * 64 * 128, attS + l * 128, attD + l * 128);
        k_attn<<<4096, 256>>>(hout, gbias + l * 64, l);
        float* t = hin; hin = hout; hout = t;
    }
    k_pspd<<<128, 256>>>(hin, W1);
    k_head<<<65536, 256>>>(ei, ea, W1, b1, W2, b2, out);
}

// round 4
// speedup vs baseline: 2.0512x; 1.0195x over previous
#include <cuda_runtime.h>

#define N_NODES 32768
#define N_EDGES 524288
#define F_DIM   64
#define D_DIM   64
#define ED_DIM  32
#define L_LAYERS 6
#define TOT (N_EDGES + N_NODES)   // edges + self loops

// ---------------- scratch (static device globals; no allocation) -------------
__device__ float g_h      [N_NODES * D_DIM];
__device__ float g_h2     [N_NODES * D_DIM];
__device__ float g_xh     [N_NODES * 128];      // [N, H*C]
__device__ float g_asd    [N_NODES * 4];        // as_h0, as_h1, ad_h0, ad_h1
__device__ float g_ae_all [N_EDGES * 12];       // per edge: 6 layers x 2 heads
__device__ float g_ve     [L_LAYERS * 2 * ED_DIM]; // lin_edge_W @ att_edge
__device__ float g_wbuf   [TOT * 2];            // softmax scratch (slow path only)
__device__ float g_pspd   [N_NODES * 128];      // [N, ps(64) | pd(64)]
__device__ int   g_deg    [N_NODES];
__device__ int   g_rowptr [N_NODES + 1];
__device__ int   g_cnt    [N_NODES];
__device__ int2  g_csr    [TOT];                // (src, eid) packed

// ---------------- setup kernels ----------------------------------------------

__global__ void k_zero() {
    int i = blockIdx.x * blockDim.x + threadIdx.x;
    if (i < N_NODES) { g_deg[i] = 0; g_cnt[i] = 0; }
}

__global__ void k_deg(const int* __restrict__ ei) {
    int e = blockIdx.x * blockDim.x + threadIdx.x;
    if (e >= N_EDGES) return;
    atomicAdd(&g_deg[ei[N_EDGES + e]], 1);
}

// exclusive scan of (deg+1); 1024 threads, warp-shuffle based
__global__ void k_scan() {
    __shared__ int wsum[32];
    int t = threadIdx.x, lane = t & 31, w = t >> 5;
    int base = t * 32;
    int vals[32]; int s = 0;
    #pragma unroll
    for (int i = 0; i < 32; i++) { vals[i] = g_deg[base + i] + 1; s += vals[i]; }
    int inc = s;
    #pragma unroll
    for (int off = 1; off < 32; off <<= 1) {
        int v = __shfl_up_sync(~0u, inc, off);
        if (lane >= off) inc += v;
    }
    if (lane == 31) wsum[w] = inc;
    __syncthreads();
    if (w == 0) {
        int v = wsum[lane], vi = v;
        #pragma unroll
        for (int off = 1; off < 32; off <<= 1) {
            int u = __shfl_up_sync(~0u, vi, off);
            if (lane >= off) vi += u;
        }
        wsum[lane] = vi;
    }
    __syncthreads();
    int run = (w > 0 ? wsum[w - 1] : 0) + (inc - s);
    #pragma unroll
    for (int i = 0; i < 32; i++) { g_rowptr[base + i] = run; run += vals[i]; }
    if (t == 1023) g_rowptr[N_NODES] = run;
}

__global__ void k_place(const int* __restrict__ ei) {
    int i = blockIdx.x * blockDim.x + threadIdx.x;
    if (i < N_EDGES) {
        int dst = ei[N_EDGES + i];
        int pos = g_rowptr[dst] + atomicAdd(&g_cnt[dst], 1);
        g_csr[pos] = make_int2(ei[i], i);
    } else if (i < TOT) {
        int n = i - N_EDGES;
        int pos = g_rowptr[n] + g_deg[n];
        g_csr[pos] = make_int2(n, N_EDGES + n);
    }
}

// ve[l,h,:] = lin_edge_W[l,:,h*64:(h+1)*64] @ att_edge[l,h,:]
__global__ void k_ve(const float* __restrict__ linE, const float* __restrict__ attE) {
    int i = threadIdx.x;
    if (i >= L_LAYERS * 64) return;
    int l = i >> 6, r = i & 63;
    int h = r >> 5, ed = r & 31;
    const float* W = linE + l * ED_DIM * 128 + ed * 128 + h * 64;
    const float* a = attE + l * 128 + h * 64;
    float s = 0.f;
    #pragma unroll
    for (int c = 0; c < 64; c++) s += W[c] * a[c];
    g_ve[l * 64 + h * 32 + ed] = s;
}

// all-layer edge attention logits in one pass over edge_attr
__global__ void k_ae_all(const float* __restrict__ ea) {
    __shared__ float sv[384];
    for (int i = threadIdx.x; i < 384; i += blockDim.x) sv[i] = g_ve[i];
    __syncthreads();
    int e = blockIdx.x * blockDim.x + threadIdx.x;
    if (e >= N_EDGES) return;
    float v[32];
    const float4* p = (const float4*)(ea + (size_t)e * 32);
    #pragma unroll
    for (int i = 0; i < 8; i++) {
        float4 q = p[i];
        v[4 * i] = q.x; v[4 * i + 1] = q.y; v[4 * i + 2] = q.z; v[4 * i + 3] = q.w;
    }
    float o[12];
    #pragma unroll
    for (int c = 0; c < 12; c++) {
        int l = c >> 1, h = c & 1;
        const float* vv = sv + l * 64 + h * 32;
        float s = 0.f;
        #pragma unroll
        for (int k = 0; k < 32; k++) s += v[k] * vv[k];
        o[c] = s;
    }
    float4* op = (float4*)(g_ae_all + (size_t)e * 12);
    op[0] = make_float4(o[0], o[1], o[2], o[3]);
    op[1] = make_float4(o[4], o[5], o[6], o[7]);
    op[2] = make_float4(o[8], o[9], o[10], o[11]);
}

// ---------------- dense kernels (register-tiled, node per thread) ------------

__global__ void k_embed(const float* __restrict__ x, const float* __restrict__ W,
                        const float* __restrict__ b, float* __restrict__ hout) {
    __shared__ float sW[64 * 64];
    __shared__ float sB[64];
    for (int i = threadIdx.x; i < 64 * 64; i += 256) sW[i] = W[i];
    if (threadIdx.x < 64) sB[threadIdx.x] = b[threadIdx.x];
    __syncthreads();
    int n = blockIdx.x * 256 + threadIdx.x;
    float h[64];
    const float4* hp = (const float4*)(x + (size_t)n * 64);
    #pragma unroll
    for (int i = 0; i < 16; i++) {
        float4 q = hp[i];
        h[4 * i] = q.x; h[4 * i + 1] = q.y; h[4 * i + 2] = q.z; h[4 * i + 3] = q.w;
    }
    #pragma unroll 2
    for (int jg = 0; jg < 16; jg++) {
        float a0 = sB[jg * 4], a1 = sB[jg * 4 + 1], a2 = sB[jg * 4 + 2], a3 = sB[jg * 4 + 3];
        #pragma unroll
        for (int d = 0; d < 64; d++) {
            float4 w = *(const float4*)&sW[d * 64 + jg * 4];
            a0 += h[d] * w.x; a1 += h[d] * w.y; a2 += h[d] * w.z; a3 += h[d] * w.w;
        }
        *(float4*)&hout[(size_t)n * 64 + jg * 4] = make_float4(a0, a1, a2, a3);
    }
}

// Fused: LayerNorm + manual modulation + xh GEMM (64->128) + a_s/a_d dots.
// Node per thread; LN is a sequential in-register reduction.
__global__ void k_lnxh(const float* __restrict__ hin,
                       const float* __restrict__ g,  const float* __restrict__ bta,
                       const float* __restrict__ mg, const float* __restrict__ mb,
                       const float* __restrict__ W,
                       const float* __restrict__ attS, const float* __restrict__ attD) {
    __shared__ float sW[64 * 128];
    __shared__ float sA[256];     // [0:128) att_src, [128:256) att_dst
    __shared__ float sGa[64];     // mg*g
    __shared__ float sCc[64];     // mg*beta + mb
    for (int i = threadIdx.x; i < 8192; i += 256) sW[i] = W[i];
    if (threadIdx.x < 128) {
        sA[threadIdx.x] = attS[threadIdx.x];
        sA[128 + threadIdx.x] = attD[threadIdx.x];
    }
    if (threadIdx.x < 64) {
        float m = mg[threadIdx.x];
        sGa[threadIdx.x] = m * g[threadIdx.x];
        sCc[threadIdx.x] = m * bta[threadIdx.x] + mb[threadIdx.x];
    }
    __syncthreads();
    int n = blockIdx.x * 256 + threadIdx.x;
    float h[64];
    const float4* hp = (const float4*)(hin + (size_t)n * 64);
    #pragma unroll
    for (int i = 0; i < 16; i++) {
        float4 q = hp[i];
        h[4 * i] = q.x; h[4 * i + 1] = q.y; h[4 * i + 2] = q.z; h[4 * i + 3] = q.w;
    }
    // in-register LayerNorm
    float s = 0.f;
    #pragma unroll
    for (int d = 0; d < 64; d++) s += h[d];
    float mu = s * (1.f / 64.f);
    float q = 0.f;
    #pragma unroll
    for (int d = 0; d < 64; d++) { h[d] -= mu; q += h[d] * h[d]; }
    float rs = rsqrtf(q * (1.f / 64.f) + 1e-5f);
    #pragma unroll
    for (int d = 0; d < 64; d++) h[d] = sGa[d] * rs * h[d] + sCc[d];
    // GEMM + attention dots
    float as0 = 0.f, as1 = 0.f, ad0 = 0.f, ad1 = 0.f;
    for (int jg = 0; jg < 32; jg++) {
        float a0 = 0.f, a1 = 0.f, a2 = 0.f, a3 = 0.f;
        #pragma unroll
        for (int d = 0; d < 64; d++) {
            float4 w = *(const float4*)&sW[d * 128 + jg * 4];
            a0 += h[d] * w.x; a1 += h[d] * w.y; a2 += h[d] * w.z; a3 += h[d] * w.w;
        }
        *(float4*)&g_xh[(size_t)n * 128 + jg * 4] = make_float4(a0, a1, a2, a3);
        int j = jg * 4;
        float ss = a0 * sA[j] + a1 * sA[j + 1] + a2 * sA[j + 2] + a3 * sA[j + 3];
        float dd = a0 * sA[128 + j] + a1 * sA[128 + j + 1] + a2 * sA[128 + j + 2] + a3 * sA[128 + j + 3];
        if (jg < 16) { as0 += ss; ad0 += dd; } else { as1 += ss; ad1 += dd; }
    }
    *(float4*)&g_asd[(size_t)n * 4] = make_float4(as0, as1, ad0, ad1);
}

// ---------------- fused segment softmax + aggregation ------------------------
// Self-loop logit = mean of the row's real-edge logits (computed in-warp).
// Aggregation: lane owns 4 contiguous channels (float4); head mean via shfl_xor(16).

__global__ void k_attn(float* __restrict__ hout, const float* __restrict__ gbias, int l) {
    int n    = (blockIdx.x * blockDim.x + threadIdx.x) >> 5;
    int lane = threadIdx.x & 31;
    if (n >= N_NODES) return;
    int row = g_rowptr[n], end = g_rowptr[n + 1];
    int cnt = end - row;                 // deg + 1 (self loop in last slot)
    float ad0 = g_asd[n * 4 + 2], ad1 = g_asd[n * 4 + 3];
    float invdeg = 1.f / fmaxf((float)(cnt - 1), 1.f);

    float4 acc = make_float4(0.f, 0.f, 0.f, 0.f);
    const float4* xbase = (const float4*)g_xh;

    if (cnt <= 32) {
        // -------- fast path: everything in lane registers --------
        bool active = (lane < cnt);
        bool isloop = (lane == cnt - 1);
        int sidx = 0;
        float b0 = 0.f, b1 = 0.f;
        if (active) {
            int2 se = g_csr[row + lane];
            sidx = se.x;
            if (!isloop) {
                const float* ap = g_ae_all + (size_t)se.y * 12 + l * 2;
                b0 = ap[0]; b1 = ap[1];
            }
        }
        // self-loop logit = mean of real-edge logits
        float sb0 = b0, sb1 = b1;
        #pragma unroll
        for (int o = 16; o; o >>= 1) {
            sb0 += __shfl_xor_sync(~0u, sb0, o);
            sb1 += __shfl_xor_sync(~0u, sb1, o);
        }
        if (isloop) { b0 = sb0 * invdeg; b1 = sb1 * invdeg; }

        float l0 = -1e30f, l1 = -1e30f;
        if (active) {
            float2 as = *(const float2*)&g_asd[sidx * 4];
            l0 = as.x + ad0 + b0;
            l1 = as.y + ad1 + b1;
            l0 = (l0 > 0.f) ? l0 : 0.2f * l0;
            l1 = (l1 > 0.f) ? l1 : 0.2f * l1;
        }
        float m0 = l0, m1 = l1;
        #pragma unroll
        for (int o = 16; o; o >>= 1) {
            m0 = fmaxf(m0, __shfl_xor_sync(~0u, m0, o));
            m1 = fmaxf(m1, __shfl_xor_sync(~0u, m1, o));
        }
        float e0 = active ? __expf(l0 - m0) : 0.f;
        float e1 = active ? __expf(l1 - m1) : 0.f;
        float s0 = e0, s1 = e1;
        #pragma unroll
        for (int o = 16; o; o >>= 1) {
            s0 += __shfl_xor_sync(~0u, s0, o);
            s1 += __shfl_xor_sync(~0u, s1, o);
        }
        float w0 = e0 / (s0 + 1e-16f);
        float w1 = e1 / (s1 + 1e-16f);

        for (int i = 0; i < cnt; i++) {
            int   si  = __shfl_sync(~0u, sidx, i);
            float w0i = __shfl_sync(~0u, w0, i);
            float w1i = __shfl_sync(~0u, w1, i);
            float ww  = (lane < 16) ? w0i : w1i;
            float4 v = xbase[(size_t)si * 32 + lane];
            acc.x += v.x * ww; acc.y += v.y * ww;
            acc.z += v.z * ww; acc.w += v.w * ww;
        }
    } else {
        // -------- slow path: spill logits to wbuf --------
        float pb0 = 0.f, pb1 = 0.f;     // sums of real-edge logits
        float m0 = -1e30f, m1 = -1e30f;
        for (int i = row + lane; i < end; i += 32) {
            int2 se = g_csr[i];
            float b0 = 0.f, b1 = 0.f;
            if (se.y < N_EDGES) {
                const float* ap = g_ae_all + (size_t)se.y * 12 + l * 2;
                b0 = ap[0]; b1 = ap[1];
                pb0 += b0; pb1 += b1;
            }
            float2 as = *(const float2*)&g_asd[se.x * 4];
            float a0 = as.x + ad0 + b0;
            float a1 = as.y + ad1 + b1;
            a0 = (a0 > 0.f) ? a0 : 0.2f * a0;
            a1 = (a1 > 0.f) ? a1 : 0.2f * a1;
            g_wbuf[i * 2] = a0; g_wbuf[i * 2 + 1] = a1;
            m0 = fmaxf(m0, a0); m1 = fmaxf(m1, a1);
        }
        #pragma unroll
        for (int o = 16; o; o >>= 1) {
            pb0 += __shfl_xor_sync(~0u, pb0, o);
            pb1 += __shfl_xor_sync(~0u, pb1, o);
        }
        // fix self-loop slot (index end-1)
        if (lane == ((end - 1 - row) & 31)) {
            float b0 = pb0 * invdeg, b1 = pb1 * invdeg;
            float2 as = *(const float2*)&g_asd[n * 4];
            float a0 = as.x + ad0 + b0;
            float a1 = as.y + ad1 + b1;
            a0 = (a0 > 0.f) ? a0 : 0.2f * a0;
            a1 = (a1 > 0.f) ? a1 : 0.2f * a1;
            g_wbuf[(end - 1) * 2] = a0; g_wbuf[(end - 1) * 2 + 1] = a1;
            m0 = fmaxf(m0, a0); m1 = fmaxf(m1, a1);
        }
        #pragma unroll
        for (int o = 16; o; o >>= 1) {
            m0 = fmaxf(m0, __shfl_xor_sync(~0u, m0, o));
            m1 = fmaxf(m1, __shfl_xor_sync(~0u, m1, o));
        }
        __syncwarp();
        float s0 = 0.f, s1 = 0.f;
        for (int i = row + lane; i < end; i += 32) {
            float e0 = __expf(g_wbuf[i * 2]     - m0);
            float e1 = __expf(g_wbuf[i * 2 + 1] - m1);
            g_wbuf[i * 2] = e0; g_wbuf[i * 2 + 1] = e1;
            s0 += e0; s1 += e1;
        }
        #pragma unroll
        for (int o = 16; o; o >>= 1) {
            s0 += __shfl_xor_sync(~0u, s0, o);
            s1 += __shfl_xor_sync(~0u, s1, o);
        }
        float inv0 = 1.f / (s0 + 1e-16f), inv1 = 1.f / (s1 + 1e-16f);
        __syncwarp();
        for (int i = row; i < end; i++) {
            int si = g_csr[i].x;
            float w0 = g_wbuf[i * 2] * inv0;
            float w1 = g_wbuf[i * 2 + 1] * inv1;
            float ww = (lane < 16) ? w0 : w1;
            float4 v = xbase[(size_t)si * 32 + lane];
            acc.x += v.x * ww; acc.y += v.y * ww;
            acc.z += v.z * ww; acc.w += v.w * ww;
        }
    }

    // head mean: lane pairs (l, l+16) hold head0/head1 of the same 4 channels
    float4 oth;
    oth.x = __shfl_xor_sync(~0u, acc.x, 16);
    oth.y = __shfl_xor_sync(~0u, acc.y, 16);
    oth.z = __shfl_xor_sync(~0u, acc.z, 16);
    oth.w = __shfl_xor_sync(~0u, acc.w, 16);
    if (lane < 16) {
        float4 bb = ((const float4*)gbias)[lane];
        float4 o;
        o.x = fmaxf(0.5f * (acc.x + oth.x) + bb.x, 0.f);
        o.y = fmaxf(0.5f * (acc.y + oth.y) + bb.y, 0.f);
        o.z = fmaxf(0.5f * (acc.z + oth.z) + bb.z, 0.f);
        o.w = fmaxf(0.5f * (acc.w + oth.w) + bb.w, 0.f);
        ((float4*)(hout + (size_t)n * 64))[lane] = o;
    }
}

// ---------------- edge head ---------------------------------------------------

// ps = h@W1[0:64], pd = h@W1[64:128]; stored [N, ps|pd]
__global__ void k_pspd(const float* __restrict__ hfin, const float* __restrict__ W1) {
    __shared__ float sW[8192];
    for (int i = threadIdx.x; i < 8192; i += 256) {
        int d = i >> 7, j = i & 127;
        sW[i] = (j < 64) ? W1[d * 64 + j] : W1[(64 + d) * 64 + (j - 64)];
    }
    __syncthreads();
    int n = blockIdx.x * 256 + threadIdx.x;
    float h[64];
    const float4* hp = (const float4*)(hfin + (size_t)n * 64);
    #pragma unroll
    for (int i = 0; i < 16; i++) {
        float4 q = hp[i];
        h[4 * i] = q.x; h[4 * i + 1] = q.y; h[4 * i + 2] = q.z; h[4 * i + 3] = q.w;
    }
    for (int jg = 0; jg < 32; jg++) {
        float a0 = 0.f, a1 = 0.f, a2 = 0.f, a3 = 0.f;
        #pragma unroll
        for (int d = 0; d < 64; d++) {
            float4 w = *(const float4*)&sW[d * 128 + jg * 4];
            a0 += h[d] * w.x; a1 += h[d] * w.y; a2 += h[d] * w.z; a3 += h[d] * w.w;
        }
        *(float4*)&g_pspd[(size_t)n * 128 + jg * 4] = make_float4(a0, a1, a2, a3);
    }
}

// per-edge head: hid = relu(ps[src]+pd[dst]+ea@Ce+b1); out = hid@W2+b2
__global__ void k_head(const int* __restrict__ ei, const float* __restrict__ ea,
                       const float* __restrict__ W1, const float* __restrict__ b1,
                       const float* __restrict__ W2, const float* __restrict__ b2,
                       float* __restrict__ out) {
    __shared__ float sC[32 * 64];
    __shared__ float sW2[64];
    __shared__ float sB1[64];
    for (int i = threadIdx.x; i < 32 * 64; i += 256) sC[i] = W1[128 * 64 + i];
    if (threadIdx.x < 64) { sW2[threadIdx.x] = W2[threadIdx.x]; sB1[threadIdx.x] = b1[threadIdx.x]; }
    __syncthreads();
    int e    = (blockIdx.x * blockDim.x + threadIdx.x) >> 5;
    int lane = threadIdx.x & 31;
    if (e >= N_EDGES) return;
    int src = ei[e], dst = ei[N_EDGES + e];
    float2 t  = *(const float2*)&g_pspd[(size_t)src * 128 + 2 * lane];
    float2 td = *(const float2*)&g_pspd[(size_t)dst * 128 + 64 + 2 * lane];
    float2 bb = *(const float2*)&sB1[2 * lane];
    t.x += td.x + bb.x;
    t.y += td.y + bb.y;
    float eav = ea[(size_t)e * 32 + lane];
    #pragma unroll
    for (int k = 0; k < 32; k++) {
        float x = __shfl_sync(~0u, eav, k);
        float2 w = *(const float2*)&sC[k * 64 + 2 * lane];
        t.x += x * w.x;
        t.y += x * w.y;
    }
    t.x = fmaxf(t.x, 0.f); t.y = fmaxf(t.y, 0.f);
    float2 w2 = *(const float2*)&sW2[2 * lane];
    float r = t.x * w2.x + t.y * w2.y;
    #pragma unroll
    for (int o = 16; o; o >>= 1) r += __shfl_xor_sync(~0u, r, o);
    if (lane == 0) out[e] = r + b2[0];
}

// ---------------- launch ------------------------------------------------------

extern "C" void kernel_launch(void* const* d_in, const int* in_sizes, int n_in,
                              void* d_out, int out_size) {
    const float* x      = (const float*)d_in[0];
    const int*   ei     = (const int*)  d_in[1];
    const float* ea     = (const float*)d_in[2];
    const float* mgamma = (const float*)d_in[3];
    const float* mbeta  = (const float*)d_in[4];
    const float* embW   = (const float*)d_in[5];
    const float* embB   = (const float*)d_in[6];
    const float* lng    = (const float*)d_in[7];
    const float* lnb    = (const float*)d_in[8];
    const float* linW   = (const float*)d_in[9];
    const float* linEW  = (const float*)d_in[10];
    const float* attS   = (const float*)d_in[11];
    const float* attD   = (const float*)d_in[12];
    const float* attE   = (const float*)d_in[13];
    const float* gbias  = (const float*)d_in[14];
    const float* W1     = (const float*)d_in[15];
    const float* b1     = (const float*)d_in[16];
    const float* W2     = (const float*)d_in[17];
    const float* b2     = (const float*)d_in[18];
    float* out = (float*)d_out;

    float *ph, *ph2;
    cudaGetSymbolAddress((void**)&ph,  g_h);
    cudaGetSymbolAddress((void**)&ph2, g_h2);

    k_zero<<<128, 256>>>();
    k_deg<<<2048, 256>>>(ei);
    k_scan<<<1, 1024>>>();
    k_place<<<(TOT + 255) / 256, 256>>>(ei);
    k_ve<<<1, 384>>>(linEW, attE);
    k_ae_all<<<2048, 256>>>(ea);
    k_embed<<<128, 256>>>(x, embW, embB, ph);

    float* hin = ph;
    float* hout = ph2;
    for (int l = 0; l < L_LAYERS; l++) {
        k_lnxh<<<128, 256>>>(hin, lng + l * 64, lnb + l * 64,
                             mgamma + l * 64, mbeta + l * 64,
                             linW + (size_t)l * 64 * 128,
                             attS + l * 128, attD + l * 128);
        k_attn<<<4096, 256>>>(hout, gbias + l * 64, l);
        float* t = hin; hin = hout; hout = t;
    }
    k_pspd<<<128, 256>>>(hin, W1);
    k_head<<<65536, 256>>>(ei, ea, W1, b1, W2, b2, out);
}